// round 13
// baseline (speedup 1.0000x reference)
#include <cuda_runtime.h>

typedef unsigned long long ull;

#define C 256
#define HW 2304
#define NTOT 3060
#define NHEAD 8

// ---------------- scratch (static device globals; no allocation) ----------------
__device__ __align__(256) float g_xs [NTOT*C];  // [n][c] rows: scale0 = x^T, then downsampled scales
__device__ __align__(256) float g_q  [NTOT*C];
__device__ __align__(256) float g_k  [NTOT*C];
__device__ __align__(256) float g_v  [NTOT*C];
__device__ __align__(256) float g_o  [NTOT*C];
__device__ __align__(256) float g_y  [NTOT*C];
__device__ __align__(256) float g_out[HW*C];    // [n][c] multiscale sum, then gated value in-place
__device__ __align__(256) float g_po [4][NTOT*C];  // key-split partial o (unnormalized)
__device__ __align__(256) float g_pl [4][NTOT*NHEAD]; // key-split partial l
__device__ float g_part[36*C];
__device__ float g_cw[C];
__device__ float g_red[72];
__device__ float g_stats[2];

__constant__ int c_off[4] = {0, 2304, 2880, 3024};
__constant__ int c_N [4]  = {2304, 576, 144, 36};
__constant__ int c_HS[4]  = {48, 24, 12, 6};

// ---------------- packed f32x2 helpers (sm_103a FFMA2 path) ----------------
__device__ __forceinline__ ull ffma2(ull a, ull b, ull c){
    ull d; asm("fma.rn.f32x2 %0,%1,%2,%3;" : "=l"(d) : "l"(a), "l"(b), "l"(c)); return d;
}
__device__ __forceinline__ ull fadd2(ull a, ull b){
    ull d; asm("add.rn.f32x2 %0,%1,%2;" : "=l"(d) : "l"(a), "l"(b)); return d;
}
__device__ __forceinline__ ull fpk(float x, float y){
    ull r; asm("mov.b64 %0,{%1,%2};" : "=l"(r) : "f"(x), "f"(y)); return r;
}
__device__ __forceinline__ float2 fupk(ull a){
    float2 r; asm("mov.b64 {%0,%1},%2;" : "=f"(r.x), "=f"(r.y) : "l"(a)); return r;
}
__device__ __forceinline__ float ex2(float x){
    float y; asm("ex2.approx.ftz.f32 %0,%1;" : "=f"(y) : "f"(x)); return y;
}

// ---------------- 1) transpose x [C][HW] -> g_xs rows 0..2303 as [n][c] ----------------
__global__ void k_transpose(const float* __restrict__ x){
    __shared__ float tile[32][33];
    int n0 = blockIdx.x * 32, c0 = blockIdx.y * 32;
    int tx = threadIdx.x, ty = threadIdx.y;
    #pragma unroll
    for (int j = 0; j < 32; j += 8)
        tile[ty + j][tx] = x[(c0 + ty + j) * HW + n0 + tx];
    __syncthreads();
    #pragma unroll
    for (int j = 0; j < 32; j += 8)
        g_xs[(n0 + ty + j) * C + c0 + tx] = tile[tx][ty + j];
}

// ---------------- 2) bilinear downsample (all reduce to 2x2 averages) ----------------
__global__ void k_down(){
    int bx = blockIdx.x, c = threadIdx.x;
    int s, nl;
    if (bx < 576)      { s = 1; nl = bx;       }
    else if (bx < 720) { s = 2; nl = bx - 576; }
    else               { s = 3; nl = bx - 720; }
    int Ws = c_HS[s];
    int ho = nl / Ws, wo = nl - ho * Ws;
    int f = 1 << s;
    int h0 = f * ho + (f >> 1) - 1;
    int w0 = f * wo + (f >> 1) - 1;
    float v = g_xs[(h0       * 48 + w0    ) * C + c]
            + g_xs[(h0       * 48 + w0 + 1) * C + c]
            + g_xs[((h0 + 1) * 48 + w0    ) * C + c]
            + g_xs[((h0 + 1) * 48 + w0 + 1) * C + c];
    g_xs[(2304 + bx) * C + c] = 0.25f * v;
}

// ---------------- 3) NT GEMM body: 64x64 tile, f32x2, W transposed in smem ----------------
__device__ __forceinline__ void gemm_body(const float* __restrict__ A,
        const float* __restrict__ W, const float* __restrict__ bias,
        float* __restrict__ O, int m0, int j0){
    __shared__ float sA[64][17];
    __shared__ float sWt[16][68];
    int tid = threadIdx.x;
    int tx = tid & 7, ty = tid >> 3;   // tx: 8 j-pairs-of-2 group, ty: 4-row m group

    ull acc[4][4];
    #pragma unroll
    for (int i = 0; i < 4; i++)
        #pragma unroll
        for (int j = 0; j < 4; j++) acc[i][j] = 0ull;

    for (int k0 = 0; k0 < 256; k0 += 16){
        #pragma unroll
        for (int r = 0; r < 2; r++){
            int idx = tid + r * 128;
            int row = idx >> 2, c4 = (idx & 3) * 4;
            float4 a4 = make_float4(0.f, 0.f, 0.f, 0.f);
            if (m0 + row < NTOT) a4 = *(const float4*)(A + (m0 + row) * 256 + k0 + c4);
            sA[row][c4] = a4.x; sA[row][c4+1] = a4.y; sA[row][c4+2] = a4.z; sA[row][c4+3] = a4.w;
            float4 w4 = *(const float4*)(W + (j0 + row) * 256 + k0 + c4);
            sWt[c4][row] = w4.x; sWt[c4+1][row] = w4.y; sWt[c4+2][row] = w4.z; sWt[c4+3][row] = w4.w;
        }
        __syncthreads();
        #pragma unroll
        for (int kk = 0; kk < 16; kk++){
            ull a2[4], w2[4];
            #pragma unroll
            for (int i = 0; i < 4; i++){ float av = sA[ty*4 + i][kk]; a2[i] = fpk(av, av); }
            #pragma unroll
            for (int j = 0; j < 4; j++) w2[j] = *(const ull*)&sWt[kk][tx*8 + 2*j];
            #pragma unroll
            for (int i = 0; i < 4; i++)
                #pragma unroll
                for (int j = 0; j < 4; j++)
                    acc[i][j] = ffma2(a2[i], w2[j], acc[i][j]);
        }
        __syncthreads();
    }
    #pragma unroll
    for (int j = 0; j < 4; j++){
        int jg = j0 + tx*8 + 2*j;
        ull b2 = *(const ull*)&bias[jg];
        #pragma unroll
        for (int i = 0; i < 4; i++){
            int m = m0 + ty*4 + i;
            if (m < NTOT) *(ull*)&O[m * 256 + jg] = fadd2(acc[i][j], b2);
        }
    }
}

__global__ void __launch_bounds__(128) k_gemm_qkv(
        const float* __restrict__ Wq, const float* __restrict__ bq,
        const float* __restrict__ Wk, const float* __restrict__ bk,
        const float* __restrict__ Wv, const float* __restrict__ bv){
    int w = blockIdx.y >> 2, jt = blockIdx.y & 3;
    const float* W = (w == 0) ? Wq : (w == 1 ? Wk : Wv);
    const float* b = (w == 0) ? bq : (w == 1 ? bk : bv);
    float* O       = (w == 0) ? g_q : (w == 1 ? g_k : g_v);
    gemm_body(g_xs, W, b, O, blockIdx.x * 64, jt * 64);
}

__global__ void __launch_bounds__(128) k_gemm_fc(const float* __restrict__ W,
                                                 const float* __restrict__ b){
    gemm_body(g_o, W, b, g_y, blockIdx.x * 64, blockIdx.y * 64);
}

// ---------------- 4) attention: 2 queries/thread, key-split, max-free softmax ----------------
// tiles: scale0: 9 q-chunks x 4 key-splits (36); scale1: 3 x 2 (6); scale2: 1; scale3: 1 => 44
__global__ void __launch_bounds__(128) k_attn(){
    __shared__ __align__(16) float sK[128 * 32];
    __shared__ __align__(16) float sV[128 * 32];
    int h = blockIdx.y, bx = blockIdx.x;
    int s, qb, ks;
    if (bx < 36)      { s = 0; qb = bx >> 2;        ks = bx & 3;        }
    else if (bx < 42) { int t = bx - 36; s = 1; qb = t >> 1; ks = t & 1; }
    else if (bx == 42){ s = 2; qb = 0; ks = 0; }
    else              { s = 3; qb = 0; ks = 0; }
    int base = c_off[s], Ns = c_N[s];
    int nsp  = (s == 0) ? 4 : (s == 1 ? 2 : 1);
    int kcnt = Ns / nsp;           // 576, 288, 144, 36 (exact)
    int kbeg = ks * kcnt;

    int qa  = qb * 256 + threadIdx.x;
    int qbn = qa + 128;
    bool va = qa  < Ns, vb = qbn < Ns;
    int rowa = base + (va ? qa  : 0);
    int rowb = base + (vb ? qbn : 0);

    const float LOG2E = 1.4426950408889634f;
    ull qra[16], qrb[16];
    {
        const float4* pa = (const float4*)(g_q + rowa * 256 + h * 32);
        const float4* pb = (const float4*)(g_q + rowb * 256 + h * 32);
        #pragma unroll
        for (int i = 0; i < 8; i++){
            float4 t = pa[i];
            qra[2*i]   = fpk(t.x * LOG2E, t.y * LOG2E);
            qra[2*i+1] = fpk(t.z * LOG2E, t.w * LOG2E);
            float4 u = pb[i];
            qrb[2*i]   = fpk(u.x * LOG2E, u.y * LOG2E);
            qrb[2*i+1] = fpk(u.z * LOG2E, u.w * LOG2E);
        }
    }
    ull oa[16], ob[16];
    #pragma unroll
    for (int i = 0; i < 16; i++){ oa[i] = 0ull; ob[i] = 0ull; }
    float la = 0.f, lb = 0.f;

    const float4* Kg = (const float4*)g_k;
    const float4* Vg = (const float4*)g_v;

    for (int kb = 0; kb < kcnt; kb += 128){
        int nk = min(128, kcnt - kb);
        __syncthreads();
        for (int idx = threadIdx.x; idx < nk * 8; idx += 128){
            int m = idx >> 3, f = idx & 7;
            int g = (base + kbeg + kb + m) * 64 + h * 8 + f;
            ((float4*)sK)[idx] = Kg[g];
            ((float4*)sV)[idx] = Vg[g];
        }
        __syncthreads();
        for (int m = 0; m < nk; m++){
            const ulonglong2* kp = (const ulonglong2*)(sK + m * 32);
            ull a0 = 0ull, a1 = 0ull, b0 = 0ull, b1 = 0ull;
            #pragma unroll
            for (int i = 0; i < 4; i++){
                ulonglong2 u = kp[2*i];
                ulonglong2 w = kp[2*i+1];
                a0 = ffma2(qra[4*i+0], u.x, a0);
                a1 = ffma2(qra[4*i+1], u.y, a1);
                a0 = ffma2(qra[4*i+2], w.x, a0);
                a1 = ffma2(qra[4*i+3], w.y, a1);
                b0 = ffma2(qrb[4*i+0], u.x, b0);
                b1 = ffma2(qrb[4*i+1], u.y, b1);
                b0 = ffma2(qrb[4*i+2], w.x, b0);
                b1 = ffma2(qrb[4*i+3], w.y, b1);
            }
            float2 fa = fupk(fadd2(a0, a1));
            float2 fb = fupk(fadd2(b0, b1));
            float ea = ex2(fa.x + fa.y);
            float eb = ex2(fb.x + fb.y);
            la += ea; lb += eb;
            ull e2a = fpk(ea, ea), e2b = fpk(eb, eb);
            const ulonglong2* vp = (const ulonglong2*)(sV + m * 32);
            #pragma unroll
            for (int i = 0; i < 8; i++){
                ulonglong2 u = vp[i];
                oa[2*i]   = ffma2(e2a, u.x, oa[2*i]);
                oa[2*i+1] = ffma2(e2a, u.y, oa[2*i+1]);
                ob[2*i]   = ffma2(e2b, u.x, ob[2*i]);
                ob[2*i+1] = ffma2(e2b, u.y, ob[2*i+1]);
            }
        }
    }
    if (va){
        ull* op = (ull*)(&g_po[ks][rowa * 256 + h * 32]);
        #pragma unroll
        for (int i = 0; i < 16; i++) op[i] = oa[i];
        g_pl[ks][rowa * 8 + h] = la;
    }
    if (vb){
        ull* op = (ull*)(&g_po[ks][rowb * 256 + h * 32]);
        #pragma unroll
        for (int i = 0; i < 16; i++) op[i] = ob[i];
        g_pl[ks][rowb * 8 + h] = lb;
    }
}

// merge key-split partials: o = sum(o_s) / sum(l_s)   (deterministic fixed order)
__global__ void k_merge(){
    int row = blockIdx.x, c = threadIdx.x;
    int hh = c >> 5;
    int ns = row < 2304 ? 4 : (row < 2880 ? 2 : 1);
    float o = 0.f, l = 0.f;
    for (int sp = 0; sp < ns; sp++){
        o += g_po[sp][row * 256 + c];
        l += g_pl[sp][row * 8 + hh];
    }
    g_o[row * 256 + c] = o / l;
}

// ---------------- 5) bilinear upsample-and-sum of all 4 scales ----------------
__global__ void k_upsample(){
    int n = blockIdx.x, c = threadIdx.x;
    int ho = n / 48, wo = n - ho * 48;
    float acc = 0.f;
    #pragma unroll
    for (int s = 0; s < 4; s++){
        int Hs = 48 >> s;
        float sc = (float)Hs * (1.f / 48.f);
        float fh = (ho + 0.5f) * sc - 0.5f;
        float fw = (wo + 0.5f) * sc - 0.5f;
        int h0 = (int)floorf(fh); float ah = fh - (float)h0;
        int w0 = (int)floorf(fw); float aw = fw - (float)w0;
        int h0c = min(Hs - 1, max(0, h0)),     h1c = min(Hs - 1, max(0, h0 + 1));
        int w0c = min(Hs - 1, max(0, w0)),     w1c = min(Hs - 1, max(0, w0 + 1));
        const float* Y = g_y + c_off[s] * C;
        float v00 = Y[(h0c * Hs + w0c) * C + c];
        float v01 = Y[(h0c * Hs + w1c) * C + c];
        float v10 = Y[(h1c * Hs + w0c) * C + c];
        float v11 = Y[(h1c * Hs + w1c) * C + c];
        acc += (1.f - ah) * ((1.f - aw) * v00 + aw * v01)
             +        ah  * ((1.f - aw) * v10 + aw * v11);
    }
    g_out[n * C + c] = acc;
}

// ---------------- 6) SE gating ----------------
__global__ void k_red1(){
    int b = blockIdx.x, c = threadIdx.x;
    float s = 0.f;
    for (int r = 0; r < 64; r++) s += g_out[(b * 64 + r) * C + c];
    g_part[b * C + c] = s;
}

__global__ void k_se(const float* __restrict__ w1, const float* __restrict__ b1,
                     const float* __restrict__ a1, const float* __restrict__ w2,
                     const float* __restrict__ b2){
    int c = threadIdx.x;
    float s = 0.f;
    for (int b = 0; b < 36; b++) s += g_part[b * C + c];
    __shared__ float avg[256];
    __shared__ float hh[16];
    avg[c] = s * (1.f / 2304.f);
    __syncthreads();
    if (c < 16){
        float a = b1[c];
        for (int j = 0; j < 256; j++) a += avg[j] * w1[c * 256 + j];
        float al = a1[0];
        hh[c] = a > 0.f ? a : al * a;
    }
    __syncthreads();
    float z = b2[c];
    #pragma unroll
    for (int j = 0; j < 16; j++) z += hh[j] * w2[c * 16 + j];
    g_cw[c] = 1.f / (1.f + __expf(-z));
}

// ---------------- 7) gate + residual and LN partial sums ----------------
__global__ void k_gate(){
    int b = blockIdx.x, c = threadIdx.x;
    float cw = g_cw[c];
    float s1 = 0.f, s2 = 0.f;
    for (int r = 0; r < 64; r++){
        int n = b * 64 + r;
        float t = g_out[n * C + c] * cw + g_xs[n * C + c];
        g_out[n * C + c] = t;
        s1 += t; s2 += t * t;
    }
    __shared__ float r1[256], r2[256];
    r1[c] = s1; r2[c] = s2;
    __syncthreads();
    for (int st = 128; st > 0; st >>= 1){
        if (c < st){ r1[c] += r1[c + st]; r2[c] += r2[c + st]; }
        __syncthreads();
    }
    if (c == 0){ g_red[b * 2] = r1[0]; g_red[b * 2 + 1] = r2[0]; }
}

__global__ void k_ln2(){
    __shared__ float s1[64], s2[64];
    int t = threadIdx.x;
    float a = 0.f, b = 0.f;
    if (t < 36){ a = g_red[2 * t]; b = g_red[2 * t + 1]; }
    s1[t] = a; s2[t] = b;
    __syncthreads();
    for (int st = 32; st > 0; st >>= 1){
        if (t < st){ s1[t] += s1[t + st]; s2[t] += s2[t + st]; }
        __syncthreads();
    }
    if (t == 0){
        float inv_n = 1.f / 589824.f;
        float mu  = s1[0] * inv_n;
        float var = s2[0] * inv_n - mu * mu;
        g_stats[0] = mu;
        g_stats[1] = rsqrtf(var + 1e-5f);
    }
}

// ---------------- 8) normalize + PReLU + transpose back to [C][H][W] ----------------
__global__ void k_final(const float* __restrict__ a2, float* __restrict__ out){
    int n = blockIdx.x, c = threadIdx.x;
    float mu = g_stats[0], inv = g_stats[1], a = a2[0];
    float t = (g_out[n * C + c] - mu) * inv;
    out[c * HW + n] = t > 0.f ? t : a * t;
}

// ---------------- launch ----------------
extern "C" void kernel_launch(void* const* d_in, const int* in_sizes, int n_in,
                              void* d_out, int out_size){
    const float* x   = (const float*)d_in[0];
    const float* Wq  = (const float*)d_in[1];
    const float* bq  = (const float*)d_in[2];
    const float* Wk  = (const float*)d_in[3];
    const float* bk  = (const float*)d_in[4];
    const float* Wv  = (const float*)d_in[5];
    const float* bv  = (const float*)d_in[6];
    const float* Wfc = (const float*)d_in[7];
    const float* bfc = (const float*)d_in[8];
    const float* w1  = (const float*)d_in[9];
    const float* b1  = (const float*)d_in[10];
    const float* a1  = (const float*)d_in[11];
    const float* w2  = (const float*)d_in[12];
    const float* b2  = (const float*)d_in[13];
    const float* a2  = (const float*)d_in[14];
    float* out = (float*)d_out;

    k_transpose<<<dim3(72, 8), dim3(32, 8)>>>(x);
    k_down<<<756, 256>>>();
    k_gemm_qkv<<<dim3(48, 12), 128>>>(Wq, bq, Wk, bk, Wv, bv);
    k_attn<<<dim3(44, 8), 128>>>();
    k_merge<<<3060, 256>>>();
    k_gemm_fc<<<dim3(48, 4), 128>>>(Wfc, bfc);
    k_upsample<<<2304, 256>>>();
    k_red1<<<36, 256>>>();
    k_se<<<1, 256>>>(w1, b1, a1, w2, b2);
    k_gate<<<36, 256>>>();
    k_ln2<<<1, 64>>>();
    k_final<<<2304, 256>>>(a2, out);
}

// round 14
// speedup vs baseline: 1.0833x; 1.0833x over previous
#include <cuda_runtime.h>

typedef unsigned long long ull;

#define C 256
#define HW 2304
#define NTOT 3060
#define NHEAD 8
#define KSPLIT0 12

// ---------------- scratch (static device globals; no allocation) ----------------
__device__ __align__(256) float g_xs [NTOT*C];  // [n][c] rows: scale0 = x^T, then downsampled scales
__device__ __align__(256) float g_q  [NTOT*C];
__device__ __align__(256) float g_k  [NTOT*C];
__device__ __align__(256) float g_v  [NTOT*C];
__device__ __align__(256) float g_o  [NTOT*C];
__device__ __align__(256) float g_y  [NTOT*C];
__device__ __align__(256) float g_out[HW*C];    // [n][c] multiscale sum, then gated value in-place
__device__ __align__(256) float g_po [KSPLIT0][NTOT*C];     // key-split partial o (unnormalized)
__device__ __align__(256) float g_pl [KSPLIT0][NTOT*NHEAD]; // key-split partial l
__device__ float g_part[36*C];
__device__ float g_cw[C];
__device__ float g_red[72];
__device__ float g_stats[2];

__constant__ int c_off[4] = {0, 2304, 2880, 3024};
__constant__ int c_N [4]  = {2304, 576, 144, 36};
__constant__ int c_HS[4]  = {48, 24, 12, 6};

// ---------------- packed f32x2 helpers (sm_103a FFMA2 path) ----------------
__device__ __forceinline__ ull ffma2(ull a, ull b, ull c){
    ull d; asm("fma.rn.f32x2 %0,%1,%2,%3;" : "=l"(d) : "l"(a), "l"(b), "l"(c)); return d;
}
__device__ __forceinline__ ull fadd2(ull a, ull b){
    ull d; asm("add.rn.f32x2 %0,%1,%2;" : "=l"(d) : "l"(a), "l"(b)); return d;
}
__device__ __forceinline__ ull fpk(float x, float y){
    ull r; asm("mov.b64 %0,{%1,%2};" : "=l"(r) : "f"(x), "f"(y)); return r;
}
__device__ __forceinline__ float2 fupk(ull a){
    float2 r; asm("mov.b64 {%0,%1},%2;" : "=f"(r.x), "=f"(r.y) : "l"(a)); return r;
}
__device__ __forceinline__ float ex2(float x){
    float y; asm("ex2.approx.ftz.f32 %0,%1;" : "=f"(y) : "f"(x)); return y;
}

// ---------------- 1) transpose x [C][HW] -> g_xs rows 0..2303 as [n][c] ----------------
__global__ void k_transpose(const float* __restrict__ x){
    __shared__ float tile[32][33];
    int n0 = blockIdx.x * 32, c0 = blockIdx.y * 32;
    int tx = threadIdx.x, ty = threadIdx.y;
    #pragma unroll
    for (int j = 0; j < 32; j += 8)
        tile[ty + j][tx] = x[(c0 + ty + j) * HW + n0 + tx];
    __syncthreads();
    #pragma unroll
    for (int j = 0; j < 32; j += 8)
        g_xs[(n0 + ty + j) * C + c0 + tx] = tile[tx][ty + j];
}

// ---------------- 2) bilinear downsample (all reduce to 2x2 averages) ----------------
__global__ void k_down(){
    int bx = blockIdx.x, c = threadIdx.x;
    int s, nl;
    if (bx < 576)      { s = 1; nl = bx;       }
    else if (bx < 720) { s = 2; nl = bx - 576; }
    else               { s = 3; nl = bx - 720; }
    int Ws = c_HS[s];
    int ho = nl / Ws, wo = nl - ho * Ws;
    int f = 1 << s;
    int h0 = f * ho + (f >> 1) - 1;
    int w0 = f * wo + (f >> 1) - 1;
    float v = g_xs[(h0       * 48 + w0    ) * C + c]
            + g_xs[(h0       * 48 + w0 + 1) * C + c]
            + g_xs[((h0 + 1) * 48 + w0    ) * C + c]
            + g_xs[((h0 + 1) * 48 + w0 + 1) * C + c];
    g_xs[(2304 + bx) * C + c] = 0.25f * v;
}

// ---------------- 3) NT GEMM body: 64x64 tile, f32x2, W transposed in smem ----------------
__device__ __forceinline__ void gemm_body(const float* __restrict__ A,
        const float* __restrict__ W, const float* __restrict__ bias,
        float* __restrict__ O, int m0, int j0){
    __shared__ float sA[64][17];
    __shared__ float sWt[16][68];
    int tid = threadIdx.x;
    int tx = tid & 7, ty = tid >> 3;   // tx: 8 j-pairs-of-2 group, ty: 4-row m group

    ull acc[4][4];
    #pragma unroll
    for (int i = 0; i < 4; i++)
        #pragma unroll
        for (int j = 0; j < 4; j++) acc[i][j] = 0ull;

    for (int k0 = 0; k0 < 256; k0 += 16){
        #pragma unroll
        for (int r = 0; r < 2; r++){
            int idx = tid + r * 128;
            int row = idx >> 2, c4 = (idx & 3) * 4;
            float4 a4 = make_float4(0.f, 0.f, 0.f, 0.f);
            if (m0 + row < NTOT) a4 = *(const float4*)(A + (m0 + row) * 256 + k0 + c4);
            sA[row][c4] = a4.x; sA[row][c4+1] = a4.y; sA[row][c4+2] = a4.z; sA[row][c4+3] = a4.w;
            float4 w4 = *(const float4*)(W + (j0 + row) * 256 + k0 + c4);
            sWt[c4][row] = w4.x; sWt[c4+1][row] = w4.y; sWt[c4+2][row] = w4.z; sWt[c4+3][row] = w4.w;
        }
        __syncthreads();
        #pragma unroll
        for (int kk = 0; kk < 16; kk++){
            ull a2[4], w2[4];
            #pragma unroll
            for (int i = 0; i < 4; i++){ float av = sA[ty*4 + i][kk]; a2[i] = fpk(av, av); }
            #pragma unroll
            for (int j = 0; j < 4; j++) w2[j] = *(const ull*)&sWt[kk][tx*8 + 2*j];
            #pragma unroll
            for (int i = 0; i < 4; i++)
                #pragma unroll
                for (int j = 0; j < 4; j++)
                    acc[i][j] = ffma2(a2[i], w2[j], acc[i][j]);
        }
        __syncthreads();
    }
    #pragma unroll
    for (int j = 0; j < 4; j++){
        int jg = j0 + tx*8 + 2*j;
        ull b2 = *(const ull*)&bias[jg];
        #pragma unroll
        for (int i = 0; i < 4; i++){
            int m = m0 + ty*4 + i;
            if (m < NTOT) *(ull*)&O[m * 256 + jg] = fadd2(acc[i][j], b2);
        }
    }
}

__global__ void __launch_bounds__(128) k_gemm_qkv(
        const float* __restrict__ Wq, const float* __restrict__ bq,
        const float* __restrict__ Wk, const float* __restrict__ bk,
        const float* __restrict__ Wv, const float* __restrict__ bv){
    int w = blockIdx.y >> 2, jt = blockIdx.y & 3;
    const float* W = (w == 0) ? Wq : (w == 1 ? Wk : Wv);
    const float* b = (w == 0) ? bq : (w == 1 ? bk : bv);
    float* O       = (w == 0) ? g_q : (w == 1 ? g_k : g_v);
    gemm_body(g_xs, W, b, O, blockIdx.x * 64, jt * 64);
}

__global__ void __launch_bounds__(128) k_gemm_fc(const float* __restrict__ W,
                                                 const float* __restrict__ b){
    gemm_body(g_o, W, b, g_y, blockIdx.x * 64, blockIdx.y * 64);
}

// ---------------- 4) attention: 2 queries/thread, 2-key pipelined, deep key-split ----------
// per head tiles: scale0: 9 q-chunks x 12 key-splits(192) = 108; scale1: 3 x 3(192) = 9;
//                 scale2: 1 (144 keys); scale3: 1 (36 keys)  => 119
__global__ void __launch_bounds__(128, 3) k_attn(){
    __shared__ __align__(16) float sK[192 * 32];
    __shared__ __align__(16) float sV[192 * 32];
    int h = blockIdx.y, bx = blockIdx.x;
    int s, qb, ks, kcnt;
    if (bx < 108)      { s = 0; qb = bx / 12; ks = bx % 12; kcnt = 192; }
    else if (bx < 117) { int t = bx - 108; s = 1; qb = t / 3; ks = t % 3; kcnt = 192; }
    else if (bx == 117){ s = 2; qb = 0; ks = 0; kcnt = 144; }
    else               { s = 3; qb = 0; ks = 0; kcnt = 36;  }
    int base = c_off[s], Ns = c_N[s];
    int kbeg = ks * kcnt;

    int qa  = qb * 256 + threadIdx.x;
    int qbn = qa + 128;
    bool va = qa  < Ns, vb = qbn < Ns;
    int rowa = base + (va ? qa  : 0);
    int rowb = base + (vb ? qbn : 0);

    const float LOG2E = 1.4426950408889634f;
    ull qra[16], qrb[16];
    {
        const float4* pa = (const float4*)(g_q + rowa * 256 + h * 32);
        const float4* pb = (const float4*)(g_q + rowb * 256 + h * 32);
        #pragma unroll
        for (int i = 0; i < 8; i++){
            float4 t = pa[i];
            qra[2*i]   = fpk(t.x * LOG2E, t.y * LOG2E);
            qra[2*i+1] = fpk(t.z * LOG2E, t.w * LOG2E);
            float4 u = pb[i];
            qrb[2*i]   = fpk(u.x * LOG2E, u.y * LOG2E);
            qrb[2*i+1] = fpk(u.z * LOG2E, u.w * LOG2E);
        }
    }

    // single-stage cooperative K/V load (whole split fits smem)
    {
        const float4* Kg = (const float4*)g_k;
        const float4* Vg = (const float4*)g_v;
        for (int idx = threadIdx.x; idx < kcnt * 8; idx += 128){
            int m = idx >> 3, f = idx & 7;
            int g = (base + kbeg + m) * 64 + h * 8 + f;
            ((float4*)sK)[idx] = Kg[g];
            ((float4*)sV)[idx] = Vg[g];
        }
    }
    __syncthreads();

    ull oa[16], ob[16];
    #pragma unroll
    for (int i = 0; i < 16; i++){ oa[i] = 0ull; ob[i] = 0ull; }
    float la = 0.f, lb = 0.f;

    for (int m = 0; m < kcnt; m += 2){
        const ulonglong2* kp0 = (const ulonglong2*)(sK + m * 32);
        const ulonglong2* kp1 = (const ulonglong2*)(sK + m * 32 + 32);
        ull a0 = 0ull, a1 = 0ull, b0 = 0ull, b1 = 0ull;   // key m  (queries a,b)
        ull c0 = 0ull, c1 = 0ull, d0 = 0ull, d1 = 0ull;   // key m+1
        #pragma unroll
        for (int i = 0; i < 4; i++){
            ulonglong2 u0 = kp0[2*i], w0 = kp0[2*i+1];
            a0 = ffma2(qra[4*i+0], u0.x, a0);
            a1 = ffma2(qra[4*i+1], u0.y, a1);
            a0 = ffma2(qra[4*i+2], w0.x, a0);
            a1 = ffma2(qra[4*i+3], w0.y, a1);
            b0 = ffma2(qrb[4*i+0], u0.x, b0);
            b1 = ffma2(qrb[4*i+1], u0.y, b1);
            b0 = ffma2(qrb[4*i+2], w0.x, b0);
            b1 = ffma2(qrb[4*i+3], w0.y, b1);
            ulonglong2 u1 = kp1[2*i], w1 = kp1[2*i+1];
            c0 = ffma2(qra[4*i+0], u1.x, c0);
            c1 = ffma2(qra[4*i+1], u1.y, c1);
            c0 = ffma2(qra[4*i+2], w1.x, c0);
            c1 = ffma2(qra[4*i+3], w1.y, c1);
            d0 = ffma2(qrb[4*i+0], u1.x, d0);
            d1 = ffma2(qrb[4*i+1], u1.y, d1);
            d0 = ffma2(qrb[4*i+2], w1.x, d0);
            d1 = ffma2(qrb[4*i+3], w1.y, d1);
        }
        float2 fa = fupk(fadd2(a0, a1));
        float2 fb = fupk(fadd2(b0, b1));
        float2 fc = fupk(fadd2(c0, c1));
        float2 fd = fupk(fadd2(d0, d1));
        float ea = ex2(fa.x + fa.y);
        float eb = ex2(fb.x + fb.y);
        float ec = ex2(fc.x + fc.y);
        float ed = ex2(fd.x + fd.y);
        la += ea; la += ec;
        lb += eb; lb += ed;
        ull e2a = fpk(ea, ea), e2b = fpk(eb, eb);
        ull e2c = fpk(ec, ec), e2d = fpk(ed, ed);
        const ulonglong2* vp0 = (const ulonglong2*)(sV + m * 32);
        const ulonglong2* vp1 = (const ulonglong2*)(sV + m * 32 + 32);
        #pragma unroll
        for (int i = 0; i < 8; i++){
            ulonglong2 u0 = vp0[i];
            ulonglong2 u1 = vp1[i];
            oa[2*i]   = ffma2(e2a, u0.x, oa[2*i]);
            oa[2*i+1] = ffma2(e2a, u0.y, oa[2*i+1]);
            ob[2*i]   = ffma2(e2b, u0.x, ob[2*i]);
            ob[2*i+1] = ffma2(e2b, u0.y, ob[2*i+1]);
            oa[2*i]   = ffma2(e2c, u1.x, oa[2*i]);
            oa[2*i+1] = ffma2(e2c, u1.y, oa[2*i+1]);
            ob[2*i]   = ffma2(e2d, u1.x, ob[2*i]);
            ob[2*i+1] = ffma2(e2d, u1.y, ob[2*i+1]);
        }
    }
    if (va){
        ull* op = (ull*)(&g_po[ks][rowa * 256 + h * 32]);
        #pragma unroll
        for (int i = 0; i < 16; i++) op[i] = oa[i];
        g_pl[ks][rowa * 8 + h] = la;
    }
    if (vb){
        ull* op = (ull*)(&g_po[ks][rowb * 256 + h * 32]);
        #pragma unroll
        for (int i = 0; i < 16; i++) op[i] = ob[i];
        g_pl[ks][rowb * 8 + h] = lb;
    }
}

// merge key-split partials: o = sum(o_s) / sum(l_s)   (deterministic fixed order)
__global__ void k_merge(){
    int row = blockIdx.x, c = threadIdx.x;
    int hh = c >> 5;
    int ns = row < 2304 ? 12 : (row < 2880 ? 3 : 1);
    float o = 0.f, l = 0.f;
    for (int sp = 0; sp < ns; sp++){
        o += g_po[sp][row * 256 + c];
        l += g_pl[sp][row * 8 + hh];
    }
    g_o[row * 256 + c] = o / l;
}

// ---------------- 5) bilinear upsample-and-sum of all 4 scales ----------------
__global__ void k_upsample(){
    int n = blockIdx.x, c = threadIdx.x;
    int ho = n / 48, wo = n - ho * 48;
    float acc = 0.f;
    #pragma unroll
    for (int s = 0; s < 4; s++){
        int Hs = 48 >> s;
        float sc = (float)Hs * (1.f / 48.f);
        float fh = (ho + 0.5f) * sc - 0.5f;
        float fw = (wo + 0.5f) * sc - 0.5f;
        int h0 = (int)floorf(fh); float ah = fh - (float)h0;
        int w0 = (int)floorf(fw); float aw = fw - (float)w0;
        int h0c = min(Hs - 1, max(0, h0)),     h1c = min(Hs - 1, max(0, h0 + 1));
        int w0c = min(Hs - 1, max(0, w0)),     w1c = min(Hs - 1, max(0, w0 + 1));
        const float* Y = g_y + c_off[s] * C;
        float v00 = Y[(h0c * Hs + w0c) * C + c];
        float v01 = Y[(h0c * Hs + w1c) * C + c];
        float v10 = Y[(h1c * Hs + w0c) * C + c];
        float v11 = Y[(h1c * Hs + w1c) * C + c];
        acc += (1.f - ah) * ((1.f - aw) * v00 + aw * v01)
             +        ah  * ((1.f - aw) * v10 + aw * v11);
    }
    g_out[n * C + c] = acc;
}

// ---------------- 6) SE gating ----------------
__global__ void k_red1(){
    int b = blockIdx.x, c = threadIdx.x;
    float s = 0.f;
    for (int r = 0; r < 64; r++) s += g_out[(b * 64 + r) * C + c];
    g_part[b * C + c] = s;
}

__global__ void k_se(const float* __restrict__ w1, const float* __restrict__ b1,
                     const float* __restrict__ a1, const float* __restrict__ w2,
                     const float* __restrict__ b2){
    int c = threadIdx.x;
    float s = 0.f;
    for (int b = 0; b < 36; b++) s += g_part[b * C + c];
    __shared__ float avg[256];
    __shared__ float hh[16];
    avg[c] = s * (1.f / 2304.f);
    __syncthreads();
    if (c < 16){
        float a = b1[c];
        for (int j = 0; j < 256; j++) a += avg[j] * w1[c * 256 + j];
        float al = a1[0];
        hh[c] = a > 0.f ? a : al * a;
    }
    __syncthreads();
    float z = b2[c];
    #pragma unroll
    for (int j = 0; j < 16; j++) z += hh[j] * w2[c * 16 + j];
    g_cw[c] = 1.f / (1.f + __expf(-z));
}

// ---------------- 7) gate + residual and LN partial sums ----------------
__global__ void k_gate(){
    int b = blockIdx.x, c = threadIdx.x;
    float cw = g_cw[c];
    float s1 = 0.f, s2 = 0.f;
    for (int r = 0; r < 64; r++){
        int n = b * 64 + r;
        float t = g_out[n * C + c] * cw + g_xs[n * C + c];
        g_out[n * C + c] = t;
        s1 += t; s2 += t * t;
    }
    __shared__ float r1[256], r2[256];
    r1[c] = s1; r2[c] = s2;
    __syncthreads();
    for (int st = 128; st > 0; st >>= 1){
        if (c < st){ r1[c] += r1[c + st]; r2[c] += r2[c + st]; }
        __syncthreads();
    }
    if (c == 0){ g_red[b * 2] = r1[0]; g_red[b * 2 + 1] = r2[0]; }
}

__global__ void k_ln2(){
    __shared__ float s1[64], s2[64];
    int t = threadIdx.x;
    float a = 0.f, b = 0.f;
    if (t < 36){ a = g_red[2 * t]; b = g_red[2 * t + 1]; }
    s1[t] = a; s2[t] = b;
    __syncthreads();
    for (int st = 32; st > 0; st >>= 1){
        if (t < st){ s1[t] += s1[t + st]; s2[t] += s2[t + st]; }
        __syncthreads();
    }
    if (t == 0){
        float inv_n = 1.f / 589824.f;
        float mu  = s1[0] * inv_n;
        float var = s2[0] * inv_n - mu * mu;
        g_stats[0] = mu;
        g_stats[1] = rsqrtf(var + 1e-5f);
    }
}

// ---------------- 8) normalize + PReLU + transpose back to [C][H][W] ----------------
__global__ void k_final(const float* __restrict__ a2, float* __restrict__ out){
    int n = blockIdx.x, c = threadIdx.x;
    float mu = g_stats[0], inv = g_stats[1], a = a2[0];
    float t = (g_out[n * C + c] - mu) * inv;
    out[c * HW + n] = t > 0.f ? t : a * t;
}

// ---------------- launch ----------------
extern "C" void kernel_launch(void* const* d_in, const int* in_sizes, int n_in,
                              void* d_out, int out_size){
    const float* x   = (const float*)d_in[0];
    const float* Wq  = (const float*)d_in[1];
    const float* bq  = (const float*)d_in[2];
    const float* Wk  = (const float*)d_in[3];
    const float* bk  = (const float*)d_in[4];
    const float* Wv  = (const float*)d_in[5];
    const float* bv  = (const float*)d_in[6];
    const float* Wfc = (const float*)d_in[7];
    const float* bfc = (const float*)d_in[8];
    const float* w1  = (const float*)d_in[9];
    const float* b1  = (const float*)d_in[10];
    const float* a1  = (const float*)d_in[11];
    const float* w2  = (const float*)d_in[12];
    const float* b2  = (const float*)d_in[13];
    const float* a2  = (const float*)d_in[14];
    float* out = (float*)d_out;

    k_transpose<<<dim3(72, 8), dim3(32, 8)>>>(x);
    k_down<<<756, 256>>>();
    k_gemm_qkv<<<dim3(48, 12), 128>>>(Wq, bq, Wk, bk, Wv, bv);
    k_attn<<<dim3(119, 8), 128>>>();
    k_merge<<<3060, 256>>>();
    k_gemm_fc<<<dim3(48, 4), 128>>>(Wfc, bfc);
    k_upsample<<<2304, 256>>>();
    k_red1<<<36, 256>>>();
    k_se<<<1, 256>>>(w1, b1, a1, w2, b2);
    k_gate<<<36, 256>>>();
    k_ln2<<<1, 64>>>();
    k_final<<<2304, 256>>>(a2, out);
}